// round 16
// baseline (speedup 1.0000x reference)
#include <cuda_runtime.h>
#include <cuda_bf16.h>
#include <math.h>
#include <stdint.h>

#define BSZ 64
#define HID 512
#define EMB 300
#define VQ  32000
#define SOS 1
#define NBLK 125
#define NCTA 125
#define NCHUNK 8

// dynamic smem layout (relative to 1024-aligned base) — as R14
#define OFF_B    32768
#define OFF_TILE 98304
#define OFF_BIAS 163840
#define OFF_RED  164864
#define OFF_LB   166912
#define OFF_GS   191488
#define OFF_BS   198016
#define OFF_IDX  198144
#define SMEM_REQ 199680

// ---------------- persistent device state ----------------
__device__ float g_hbuf[2][BSZ * HID];
__device__ float g_c[BSZ * HID];
__device__ unsigned long long g_amax[2][BSZ];
__device__ float2 g_part[2][BSZ][NBLK];
__device__ __nv_bfloat16 g_Whi[(size_t)VQ * HID];
__device__ __nv_bfloat16 g_Wlo[(size_t)VQ * HID];
__device__ __nv_bfloat16 g_Wlh[(size_t)NCTA * 24 * 896];
__device__ __nv_bfloat16 g_Wll[(size_t)NCTA * 24 * 896];
__device__ unsigned int g_bcnt;
__device__ unsigned int g_epoch;

// ---------------- helpers ----------------
__device__ __forceinline__ unsigned int fmono(float f) {
    unsigned int u = __float_as_uint(f);
    return (u & 0x80000000u) ? ~u : (u | 0x80000000u);
}
__device__ __forceinline__ float fmono_inv(unsigned int u) {
    return (u & 0x80000000u) ? __uint_as_float(u & 0x7FFFFFFFu)
                             : __uint_as_float(~u);
}
__device__ __forceinline__ float fexp(float x) {
    x = fmaxf(x, -80.0f);
    float t = fmaf(x, 1.4426950408889634f, 12582912.0f);
    float i = t - 12582912.0f;
    float f = fmaf(x, 1.4426950408889634f, -i);
    float p = 1.3333558e-3f;
    p = fmaf(p, f, 9.6181291e-3f);
    p = fmaf(p, f, 5.5504110e-2f);
    p = fmaf(p, f, 2.4022651e-1f);
    p = fmaf(p, f, 6.9314718e-1f);
    p = fmaf(p, f, 1.0f);
    int ei = __float_as_int(t) - 0x4B400000;
    float sc = __int_as_float((ei + 127) << 23);
    return sc * p;
}
__device__ __forceinline__ uint32_t smem_u32(const void* p) {
    uint32_t a;
    asm("{ .reg .u64 t; cvta.to.shared.u64 t, %1; cvt.u32.u64 %0, t; }"
        : "=r"(a) : "l"(p));
    return a;
}
__device__ __forceinline__ uint32_t sw128(uint32_t o) { return o ^ ((o >> 3) & 0x70); }
__device__ __forceinline__ uint32_t pb2(float a, float b) {
    __nv_bfloat162 t = __floats2bfloat162_rn(a, b);
    return *reinterpret_cast<uint32_t*>(&t);
}
__device__ __forceinline__ void st_cs4(float* p, float4 x) {
    asm volatile("st.global.cs.v4.f32 [%0], {%1, %2, %3, %4};"
                 :: "l"(p), "f"(x.x), "f"(x.y), "f"(x.z), "f"(x.w) : "memory");
}

// split grid barrier
__device__ __forceinline__ void g_arrive() {
    __syncthreads();
    if (threadIdx.x == 0)
        asm volatile("red.release.gpu.global.add.u32 [%0], 1;"
                     :: "l"(&g_bcnt) : "memory");
}
__device__ __forceinline__ void g_wait(unsigned int target) {
    if (threadIdx.x == 0) {
        unsigned int v;
        do {
            __nanosleep(32);
            asm volatile("ld.global.acquire.gpu.b32 %0, [%1];"
                         : "=r"(v) : "l"(&g_bcnt) : "memory");
        } while ((int)(v - target) < 0);
    }
    __syncthreads();
}

#define CP_ASYNC16(dst, src) \
    asm volatile("cp.async.cg.shared.global [%0], [%1], 16;" :: "r"(dst), "l"(src) : "memory")
#define CP_COMMIT() asm volatile("cp.async.commit_group;" ::: "memory")
#define CP_WAIT(n)  asm volatile("cp.async.wait_group %0;" :: "n"(n) : "memory")

__device__ __forceinline__ void ldsm4(uint32_t* r, uint32_t addr) {
    asm volatile("ldmatrix.sync.aligned.m8n8.x4.shared.b16 {%0,%1,%2,%3}, [%4];"
                 : "=r"(r[0]), "=r"(r[1]), "=r"(r[2]), "=r"(r[3]) : "r"(addr));
}
__device__ __forceinline__ void ldsm2(uint32_t* r, uint32_t addr) {
    asm volatile("ldmatrix.sync.aligned.m8n8.x2.shared.b16 {%0,%1}, [%2];"
                 : "=r"(r[0]), "=r"(r[1]) : "r"(addr));
}
__device__ __forceinline__ void mma16816(float* d, const uint32_t* a, const uint32_t* b) {
    asm volatile(
        "mma.sync.aligned.m16n8k16.row.col.f32.bf16.bf16.f32 "
        "{%0,%1,%2,%3}, {%4,%5,%6,%7}, {%8,%9}, {%0,%1,%2,%3};"
        : "+f"(d[0]), "+f"(d[1]), "+f"(d[2]), "+f"(d[3])
        : "r"(a[0]), "r"(a[1]), "r"(a[2]), "r"(a[3]), "r"(b[0]), "r"(b[1]));
}

// ---------------- staging: 64 x 64 fp32 -> hi/lo bf16 SW128 ----------------
__device__ __forceinline__ void stsX(uint32_t abase, const float4* av) {
    int t = threadIdx.x;
#pragma unroll
    for (int n = 0; n < 4; n++) {
        int i = t + n * 256;
        int r = i >> 4, q = i & 15;
        float4 x = av[n];
        float hx = __bfloat162float(__float2bfloat16_rn(x.x));
        float hy = __bfloat162float(__float2bfloat16_rn(x.y));
        float hz = __bfloat162float(__float2bfloat16_rn(x.z));
        float hw = __bfloat162float(__float2bfloat16_rn(x.w));
        uint32_t so = sw128((uint32_t)(r * 128 + q * 8));
        asm volatile("st.shared.v2.b32 [%0], {%1, %2};" ::
                     "r"(abase + so), "r"(pb2(hx, hy)), "r"(pb2(hz, hw)) : "memory");
        asm volatile("st.shared.v2.b32 [%0], {%1, %2};" ::
                     "r"(abase + 8192 + so),
                     "r"(pb2(x.x - hx, x.y - hy)), "r"(pb2(x.z - hz, x.w - hw)) : "memory");
    }
}

// ---------------- phase A1: tensor-core LSTM, chunk order {3,4,5,6,0,1,2} ----------------
__device__ __forceinline__ void issueLB2(uint32_t lbbase, int o, int i0) {
    int t = threadIdx.x;
#pragma unroll
    for (int n = 0; n < 2; n++) {
        int i = t + n * 256;
        if (i < 384) {
            int sub = (i >= 192) ? 1 : 0;
            int ii = i - sub * 192;
            int row = ii >> 3, j = ii & 7;
            size_t g = ((size_t)i0 * 24 + row) * 896 + (size_t)(2 * o + sub) * 64 + j * 8;
            uint32_t dst = lbbase + sub * 6144 + sw128((uint32_t)(row * 128 + j * 16));
            CP_ASYNC16(dst, g_Wlh + g);
            CP_ASYNC16(dst + 3072, g_Wll + g);
        }
    }
}
__device__ __forceinline__ void ldgX(const float* __restrict__ emb,
                                     const float* __restrict__ hin,
                                     const int* sidx, int sc, float4* av) {
    int t = threadIdx.x;
#pragma unroll
    for (int n = 0; n < 4; n++) {
        int i = t + n * 256;
        int r = i >> 4, q = i & 15;
        int k = sc * 64 + q * 4;
        float4 x;
        if (k < EMB) {
            x = *(const float4*)(emb + (size_t)sidx[r] * EMB + k);
            x.x = fmaxf(x.x, 0.f); x.y = fmaxf(x.y, 0.f);
            x.z = fmaxf(x.z, 0.f); x.w = fmaxf(x.w, 0.f);
        } else if (k < EMB + HID) {
            x = __ldcg((const float4*)(hin + r * HID + (k - EMB)));
        } else {
            x = make_float4(0.f, 0.f, 0.f, 0.f);
        }
        av[n] = x;
    }
}

// b2wait: if >=0, wait for this barrier target before the token-dependent chunks
__device__ void lstm_phase(char* smb, uint32_t base,
                           const float* __restrict__ emb,
                           const float* __restrict__ b_ih,
                           const float* __restrict__ b_hh,
                           const int*   __restrict__ qix,
                           int par, long long b2wait) {
    float* gsf = (float*)(smb + OFF_GS);    // [24][68]
    float* bsf = (float*)(smb + OFF_BS);    // [24]
    int* sidx  = (int*)(smb + OFF_IDX);

    const int t  = threadIdx.x;
    const int i0 = blockIdx.x;
    const int NU = (i0 < 12) ? 5 : 4;
    const int NR = NU * 4;

    const float* hin  = g_hbuf[par];
    float*       hout = g_hbuf[par ^ 1];

    // token-independent setup
    if (i0 == 0 && t >= 64 && t < 128) g_amax[par][t - 64] = 0ull;
    if (t < 24) {
        float v = 0.f;
        if (t < NR) {
            int gr = (t & 3) * HID + ((t >> 2) * 125 + i0);
            v = b_ih[gr] + b_hh[gr];
        }
        bsf[t] = v;
    }

    const int wid = t >> 5, ln = t & 31;
    const int mt = wid & 3;
    const int n0 = (wid >> 2) * 8;
    const bool extra = (NR == 20) && (wid < 4);

    float acc[4]  = {0.f, 0.f, 0.f, 0.f};
    float acc2[4] = {0.f, 0.f, 0.f, 0.f};

    // chunk order: h-only chunks first (3..6), then token-dependent (0..2)
    const int order[7] = {3, 4, 5, 6, 0, 1, 2};

    // prefetch chunk 3 (B via cp.async; A via regs->smem — pure h, no token dep)
    issueLB2(base + OFF_LB, 3, i0);
    CP_COMMIT();
    {
        float4 a0[4];
        ldgX(emb, hin, sidx, 6, a0); stsX(base, a0);
        ldgX(emb, hin, sidx, 7, a0); stsX(base + 16384, a0);
    }

    const int ti = ln >> 3, li = ln & 7;
    const int aml = (ti & 1) * 8 + li, ak = ti >> 1;
    const int bli = ln & 7, bsel = (ln >> 3) & 1;

    float4 ava[4], avb[4];
    for (int ci = 0; ci < 7; ci++) {
        if (ci == 3) {
            // token becomes needed at the NEXT gather (chunk 0, emb region)
            if (b2wait >= 0) g_wait((unsigned int)b2wait);
            if (t < BSZ) {
                unsigned long long key = __ldcg(&g_amax[par ^ 1][t]);
                sidx[t] = qix[~(unsigned int)(key & 0xFFFFFFFFull)];
            }
            __syncthreads();
        }
        if (ci < 6) {
            int nxt = order[ci + 1];
            issueLB2(base + OFF_LB + ((ci + 1) & 1) * 12288, nxt, i0);
            CP_COMMIT();
            ldgX(emb, hin, sidx, 2 * nxt, ava);
            ldgX(emb, hin, sidx, 2 * nxt + 1, avb);
            CP_WAIT(1);
        } else {
            CP_WAIT(0);
        }
        __syncthreads();

        uint32_t LBo = base + OFF_LB + (ci & 1) * 12288;
#pragma unroll
        for (int k8 = 0; k8 < 8; k8++) {
            int sub = k8 >> 2, kss = k8 & 3;
            uint32_t Ahi = base + sub * 16384, Alo = Ahi + 8192;
            uint32_t Bhi = LBo + sub * 6144, Blo = Bhi + 3072;
            uint32_t ah[4], al[4], bh[2], bl[2];
            uint32_t aoff = sw128((uint32_t)((mt * 16 + aml) * 128 + kss * 32 + ak * 16));
            ldsm4(ah, Ahi + aoff);
            ldsm4(al, Alo + aoff);
            uint32_t boff = sw128((uint32_t)((n0 + bli) * 128 + kss * 32 + bsel * 16));
            ldsm2(bh, Bhi + boff);
            ldsm2(bl, Blo + boff);
            mma16816(acc, ah, bh);
            mma16816(acc, ah, bl);
            mma16816(acc, al, bh);
            if (extra) {
                uint32_t boff2 = sw128((uint32_t)((16 + bli) * 128 + kss * 32 + bsel * 16));
                ldsm2(bh, Bhi + boff2);
                ldsm2(bl, Blo + boff2);
                mma16816(acc2, ah, bh);
                mma16816(acc2, ah, bl);
                mma16816(acc2, al, bh);
            }
        }
        __syncthreads();
        if (ci < 6) {
            stsX(base, ava);
            stsX(base + 16384, avb);
        }
    }

    // epilogue: frags -> gates smem (+bias)
    {
        int g = ln >> 2, c2 = (ln & 3) * 2;
        int row = mt * 16 + g;
        int col = n0 + c2;
        gsf[col * 68 + row]           = acc[0] + bsf[col];
        gsf[(col + 1) * 68 + row]     = acc[1] + bsf[col + 1];
        gsf[col * 68 + row + 8]       = acc[2] + bsf[col];
        gsf[(col + 1) * 68 + row + 8] = acc[3] + bsf[col + 1];
        if (extra) {
            int col2 = 16 + c2;
            gsf[col2 * 68 + row]           = acc2[0] + bsf[col2];
            gsf[(col2 + 1) * 68 + row]     = acc2[1] + bsf[col2 + 1];
            gsf[col2 * 68 + row + 8]       = acc2[2] + bsf[col2];
            gsf[(col2 + 1) * 68 + row + 8] = acc2[3] + bsf[col2 + 1];
        }
    }
    __syncthreads();

    // cell update (units u = j*125 + i0; exclusively owned per CTA)
    for (int p = t; p < NU * 64; p += 256) {
        int uu = p >> 6, m = p & 63;
        float gi = gsf[(uu * 4 + 0) * 68 + m];
        float gf = gsf[(uu * 4 + 1) * 68 + m];
        float gg = gsf[(uu * 4 + 2) * 68 + m];
        float go = gsf[(uu * 4 + 3) * 68 + m];
        int ci = m * HID + uu * 125 + i0;
        float c  = __ldcg(&g_c[ci]);
        float si = 1.f / (1.f + expf(-gi));
        float sf = 1.f / (1.f + expf(-gf));
        float so = 1.f / (1.f + expf(-go));
        float nc = sf * c + si * tanhf(gg);
        float nh = so * tanhf(nc);
        g_c[ci]  = nc;
        hout[ci] = nh;
    }
    // caller's g_arrive() does the closing __syncthreads
}

// ---------------- phase A2: finalize tile in smem -> out ----------------
__device__ void finalize_tile(char* smb, float* __restrict__ out,
                              int sprev, int steps) {
    const int t = threadIdx.x;
    const int w = t >> 5, ln = t & 31;
    const int pp = sprev & 1;
    const int v0 = blockIdx.x * 256;
    float* tile = (float*)(smb + OFF_TILE);
    float* lse_sm = (float*)(smb + OFF_RED);

    for (int r = w; r < BSZ; r += 8) {
        float2 pv[4];
#pragma unroll
        for (int i = 0; i < 4; i++) {
            int idx = ln + i * 32;
            pv[i] = (idx < NBLK) ? __ldcg(&g_part[pp][r][idx])
                                 : make_float2(-3.4e38f, 0.f);
        }
        float m = fmaxf(fmaxf(pv[0].x, pv[1].x), fmaxf(pv[2].x, pv[3].x));
#pragma unroll
        for (int o = 16; o >= 1; o >>= 1)
            m = fmaxf(m, __shfl_xor_sync(0xFFFFFFFFu, m, o));
        float s = pv[0].y * fexp(pv[0].x - m) + pv[1].y * fexp(pv[1].x - m)
                + pv[2].y * fexp(pv[2].x - m) + pv[3].y * fexp(pv[3].x - m);
#pragma unroll
        for (int o = 16; o >= 1; o >>= 1)
            s += __shfl_xor_sync(0xFFFFFFFFu, s, o);
        if (ln == 0) lse_sm[r] = m + logf(s);
    }
    __syncthreads();

#pragma unroll 4
    for (int it = 0; it < 16; it++) {
        int idx = t + it * 256;
        int r  = idx >> 6;
        int c4 = idx & 63;
        float4 x = *(const float4*)&tile[r * 256 + c4 * 4];
        float lse = lse_sm[r];
        x.x -= lse; x.y -= lse; x.z -= lse; x.w -= lse;
        st_cs4(out + ((size_t)r * steps + sprev) * VQ + v0 + c4 * 4, x);
    }
    __syncthreads();   // TILE fully read before buf1 reuse
}

// ---------------- phase B: logits GEMM + fragment epilogue ----------------
__device__ __forceinline__ void issueB(uint32_t bbase, int c, int v0) {
    int t = threadIdx.x;
#pragma unroll
    for (int n = 0; n < 8; n++) {
        int i = t + n * 256;
        int r = i >> 3, j = i & 7;
        size_t g = (size_t)(v0 + r) * HID + (size_t)c * 64 + j * 8;
        uint32_t so = sw128((uint32_t)(r * 128 + j * 16));
        CP_ASYNC16(bbase + so, g_Whi + g);
        CP_ASYNC16(bbase + 32768 + so, g_Wlo + g);
    }
}
__device__ __forceinline__ void ldgA(const float* h, int c, float4* av) {
    int t = threadIdx.x;
#pragma unroll
    for (int n = 0; n < 4; n++) {
        int i = t + n * 256;
        int r = i >> 4, q = i & 15;
        av[n] = __ldcg((const float4*)&h[r * HID + c * 64 + q * 4]);
    }
}

__device__ void logits_phase(char* smb, uint32_t base, int par) {
    const int t  = threadIdx.x;
    const int wid = t >> 5, ln = t & 31;
    const int v0 = blockIdx.x * 256;
    const float* h = g_hbuf[par ^ 1];
    float* bias_sm = (float*)(smb + OFF_BIAS);

    float acc[4][4][4];
#pragma unroll
    for (int a = 0; a < 4; a++)
#pragma unroll
        for (int b = 0; b < 4; b++)
#pragma unroll
            for (int cc = 0; cc < 4; cc++) acc[a][b][cc] = 0.f;

    {
        float4 av0[4];
        ldgA(h, 0, av0);
        stsX(base, av0);
    }

    const int ti = ln >> 3, li = ln & 7;
    const int aml = (ti & 1) * 8 + li, ak = ti >> 1;
    const int bnl = (ti >> 1) * 8 + li, bk = ti & 1;
    const int nbase = wid * 32;

    float4 av[4];
    for (int c = 0; c < NCHUNK; c++) {
        int b = c & 1;
        if (c >= 1 && c < NCHUNK - 1) {
            issueB(base + OFF_B + (b ^ 1) * 65536, c + 1, v0);
            CP_COMMIT();
        }
        if (c < NCHUNK - 1) {
            ldgA(h, c + 1, av);
            CP_WAIT(1);
        } else {
            CP_WAIT(0);
        }
        __syncthreads();

        uint32_t Ahi = base + b * 16384, Alo = Ahi + 8192;
        uint32_t Bhi = base + OFF_B + b * 65536, Blo = Bhi + 32768;
#pragma unroll
        for (int ks = 0; ks < 4; ks++) {
            uint32_t ah[4][4], al[4][4], bh[4][2], bl[4][2];
#pragma unroll
            for (int mt = 0; mt < 4; mt++) {
                uint32_t off = sw128((uint32_t)((mt * 16 + aml) * 128 + ks * 32 + ak * 16));
                ldsm4(ah[mt], Ahi + off);
                ldsm4(al[mt], Alo + off);
            }
#pragma unroll
            for (int ng = 0; ng < 2; ng++) {
                uint32_t off = sw128((uint32_t)((nbase + ng * 16 + bnl) * 128 + ks * 32 + bk * 16));
                uint32_t r4[4];
                ldsm4(r4, Bhi + off);
                bh[ng * 2][0] = r4[0]; bh[ng * 2][1] = r4[1];
                bh[ng * 2 + 1][0] = r4[2]; bh[ng * 2 + 1][1] = r4[3];
                ldsm4(r4, Blo + off);
                bl[ng * 2][0] = r4[0]; bl[ng * 2][1] = r4[1];
                bl[ng * 2 + 1][0] = r4[2]; bl[ng * 2 + 1][1] = r4[3];
            }
#pragma unroll
            for (int mt = 0; mt < 4; mt++)
#pragma unroll
                for (int nt = 0; nt < 4; nt++) {
                    mma16816(acc[mt][nt], ah[mt], bh[nt]);
                    mma16816(acc[mt][nt], ah[mt], bl[nt]);
                    mma16816(acc[mt][nt], al[mt], bh[nt]);
                }
        }
        if (c < NCHUNK - 1) stsX(base + (b ^ 1) * 16384, av);
        __syncthreads();
    }

    // epilogue from fragments: tile store + per-warp slab partials
    float* tile = (float*)(smb + OFF_TILE);
    unsigned long long* pmk = (unsigned long long*)(smb + OFF_GS);  // [64][8]
    float* pms = (float*)(smb + OFF_GS + 4096);                     // [64][8]
    const int g = ln >> 2, tg2 = (ln & 3) * 2;
#pragma unroll
    for (int mt = 0; mt < 4; mt++) {
#pragma unroll
        for (int half = 0; half < 2; half++) {
            int r = mt * 16 + g + half * 8;
            float vals[8];
#pragma unroll
            for (int nt = 0; nt < 4; nt++) {
                int col = nbase + nt * 8 + tg2;
                float va = acc[mt][nt][half * 2]     + bias_sm[col];
                float vb = acc[mt][nt][half * 2 + 1] + bias_sm[col + 1];
                vals[nt * 2] = va; vals[nt * 2 + 1] = vb;
                tile[r * 256 + col]     = va;
                tile[r * 256 + col + 1] = vb;
            }
            float vm = vals[0]; int vj = 0;
#pragma unroll
            for (int j = 1; j < 8; j++)
                if (vals[j] > vm) { vm = vals[j]; vj = j; }
            int vcol = v0 + nbase + (vj >> 1) * 8 + tg2 + (vj & 1);
            unsigned long long key =
                ((unsigned long long)fmono(vm) << 32) |
                (unsigned int)(~(unsigned int)vcol);
            {
                unsigned long long o1 = __shfl_xor_sync(0xFFFFFFFFu, key, 1);
                if (o1 > key) key = o1;
                unsigned long long o2 = __shfl_xor_sync(0xFFFFFFFFu, key, 2);
                if (o2 > key) key = o2;
            }
            float mrow = fmono_inv((unsigned int)(key >> 32));
            float s = 0.f;
#pragma unroll
            for (int j = 0; j < 8; j++) s += fexp(vals[j] - mrow);
            s += __shfl_xor_sync(0xFFFFFFFFu, s, 1);
            s += __shfl_xor_sync(0xFFFFFFFFu, s, 2);
            if ((ln & 3) == 0) {
                pmk[r * 8 + wid] = key;
                pms[r * 8 + wid] = s;
            }
        }
    }
    __syncthreads();

    if (t < 64) {
        unsigned long long key = pmk[t * 8];
#pragma unroll
        for (int i = 1; i < 8; i++) {
            unsigned long long o2 = pmk[t * 8 + i];
            if (o2 > key) key = o2;
        }
        float M = fmono_inv((unsigned int)(key >> 32));
        float s = 0.f;
#pragma unroll
        for (int i = 0; i < 8; i++) {
            float mi = fmono_inv((unsigned int)(pmk[t * 8 + i] >> 32));
            s += pms[t * 8 + i] * fexp(mi - M);
        }
        atomicMax(&g_amax[par][t], key);
        g_part[par][t][blockIdx.x] = make_float2(M, s);
    }
    // caller's g_arrive() does the closing __syncthreads
}

// ---------------- the persistent decode kernel (single launch) ----------------
__global__ void __launch_bounds__(256, 1)
k_main(const float* __restrict__ q_att,
       const float* __restrict__ emb,
       const float* __restrict__ W_ih,
       const float* __restrict__ W_hh,
       const float* __restrict__ b_ih,
       const float* __restrict__ b_hh,
       const float* __restrict__ out_W,
       const float* __restrict__ out_b,
       const int*   __restrict__ qix,
       float* __restrict__ out, int steps) {
    extern __shared__ __align__(16) char smem_raw[];
    uint32_t raw  = smem_u32(smem_raw);
    uint32_t base = (raw + 1023) & ~1023u;
    char* smb = smem_raw + (base - raw);
    const int t = threadIdx.x;
    const int v0cta = blockIdx.x * 256;

    unsigned int Eval = 0, ebase = 0;
    const unsigned int NBAR = (unsigned int)(1 + 2 * steps);
    if (t == 0) {
        asm volatile("ld.global.acquire.gpu.b32 %0, [%1];"
                     : "=r"(Eval) : "l"(&g_epoch));
        ebase = Eval * NBAR * NCTA;
    }

    // ---- prologue ----
    {
        size_t n4 = (size_t)VQ * HID / 4;
        uint2* whi = (uint2*)g_Whi;
        uint2* wlo = (uint2*)g_Wlo;
        for (size_t i = (size_t)blockIdx.x * 256 + t; i < n4; i += (size_t)NCTA * 256) {
            float4 x = ((const float4*)out_W)[i];
            float hx = __bfloat162float(__float2bfloat16_rn(x.x));
            float hy = __bfloat162float(__float2bfloat16_rn(x.y));
            float hz = __bfloat162float(__float2bfloat16_rn(x.z));
            float hw = __bfloat162float(__float2bfloat16_rn(x.w));
            whi[i] = make_uint2(pb2(hx, hy), pb2(hz, hw));
            wlo[i] = make_uint2(pb2(x.x - hx, x.y - hy), pb2(x.z - hz, x.w - hw));
        }
        {
            int NRp = ((blockIdx.x < 12) ? 5 : 4) * 4;
            for (int i = t; i < 24 * 896; i += 256) {
                int r = i / 896, k = i - r * 896;
                float v = 0.f;
                if (r < NRp && k < EMB + HID) {
                    int gr = (r & 3) * HID + ((r >> 2) * 125 + blockIdx.x);
                    v = (k < EMB) ? W_ih[(size_t)gr * EMB + k]
                                  : W_hh[(size_t)gr * HID + (k - EMB)];
                }
                float hv = __bfloat162float(__float2bfloat16_rn(v));
                size_t o = ((size_t)blockIdx.x * 24 + r) * 896 + k;
                g_Wlh[o] = __float2bfloat16_rn(v);
                g_Wll[o] = __float2bfloat16_rn(v - hv);
            }
        }
        if (blockIdx.x == 0) {
            if (t < BSZ) {
                g_amax[1][t] = (unsigned long long)(unsigned int)(~(unsigned int)SOS);
                g_amax[0][t] = 0ull;
            }
            for (int i = t; i < BSZ * HID; i += 256) {
                g_hbuf[0][i] = q_att[i];
                g_c[i] = 0.f;
            }
        }
        ((float*)(smb + OFF_BIAS))[t] = out_b[v0cta + t];
    }
    g_arrive(); g_wait(ebase + 1 * NCTA);

    // logits chunk 0 for step 0 -> buf0 (drains during lstm)
    issueB(base + OFF_B, 0, v0cta);
    CP_COMMIT();

    for (int s = 0; s < steps; s++) {
        int par = s & 1;
        // b2(s-1) target = ebase + (2s+1)*NCTA; s=0: no wait (prologue covered)
        long long b2w = (s > 0) ? (long long)(ebase + (unsigned)(2 * s + 1) * NCTA)
                                : -1;

        lstm_phase(smb, base, emb, b_ih, b_hh, qix, par, b2w);
        g_arrive();                               // b1(s): count 2s+2
        if (s > 0) finalize_tile(smb, out, s - 1, steps);
        issueB(base + OFF_B + 65536, 1, v0cta);   // chunk 1 -> buf1 (TILE consumed)
        CP_COMMIT();
        g_wait(ebase + (unsigned)(2 * s + 2) * NCTA);

        logits_phase(smb, base, par);
        g_arrive();                               // b2(s): count 2s+3
        if (s + 1 < steps) {
            issueB(base + OFF_B, 0, v0cta);       // chunk 0 next step -> buf0
            CP_COMMIT();
        }
        // NOTE: no b2 wait here — hidden inside next step's lstm
    }

    // final b2 wait: g_part/g_amax of last step complete across all CTAs
    g_wait(ebase + (unsigned)(2 * steps + 1) * NCTA);

    if (blockIdx.x == 0 && t == 0)
        *((volatile unsigned int*)&g_epoch) = Eval + 1;

    finalize_tile(smb, out, steps - 1, steps);
}

// ---------------- launch ----------------
extern "C" void kernel_launch(void* const* d_in, const int* in_sizes, int n_in,
                              void* d_out, int out_size) {
    (void)in_sizes; (void)n_in;
    const float* q_att = (const float*)d_in[1];
    const float* emb   = (const float*)d_in[2];
    const float* W_ih  = (const float*)d_in[3];
    const float* W_hh  = (const float*)d_in[4];
    const float* b_ih  = (const float*)d_in[5];
    const float* b_hh  = (const float*)d_in[6];
    const float* out_W = (const float*)d_in[7];
    const float* out_b = (const float*)d_in[8];
    const int*   qix   = (const int*)d_in[9];

    int steps = out_size / (BSZ * VQ);  // 33

    cudaFuncSetAttribute(k_main, cudaFuncAttributeMaxDynamicSharedMemorySize,
                         SMEM_REQ);

    k_main<<<NCTA, 256, SMEM_REQ>>>(q_att, emb, W_ih, W_hh, b_ih, b_hh,
                                    out_W, out_b, qix, (float*)d_out, steps);
}

// round 17
// speedup vs baseline: 1.0420x; 1.0420x over previous
#include <cuda_runtime.h>
#include <cuda_bf16.h>
#include <math.h>
#include <stdint.h>

#define BSZ 64
#define HID 512
#define EMB 300
#define VQ  32000
#define SOS 1
#define NBLK 125
#define NCTA 125
#define NCHUNK 8

// dynamic smem layout (relative to 1024-aligned base) — as R14
#define OFF_B    32768
#define OFF_TILE 98304
#define OFF_BIAS 163840
#define OFF_RED  164864
#define OFF_LB   166912
#define OFF_GS   191488
#define OFF_BS   198016
#define OFF_IDX  198144
#define SMEM_REQ 199680

// ---------------- persistent device state ----------------
__device__ float g_hbuf[2][BSZ * HID];
__device__ __nv_bfloat16 g_hhi[2][BSZ * HID];   // h split hi (per step parity)
__device__ __nv_bfloat16 g_hlo[2][BSZ * HID];   // h split lo
__device__ float g_c[BSZ * HID];
__device__ unsigned long long g_amax[2][BSZ];
__device__ float2 g_part[2][BSZ][NBLK];
__device__ __nv_bfloat16 g_Whi[(size_t)VQ * HID];
__device__ __nv_bfloat16 g_Wlo[(size_t)VQ * HID];
__device__ __nv_bfloat16 g_Wlh[(size_t)NCTA * 24 * 896];
__device__ __nv_bfloat16 g_Wll[(size_t)NCTA * 24 * 896];
__device__ unsigned int g_bcnt;
__device__ unsigned int g_epoch;

// ---------------- helpers ----------------
__device__ __forceinline__ unsigned int fmono(float f) {
    unsigned int u = __float_as_uint(f);
    return (u & 0x80000000u) ? ~u : (u | 0x80000000u);
}
__device__ __forceinline__ float fmono_inv(unsigned int u) {
    return (u & 0x80000000u) ? __uint_as_float(u & 0x7FFFFFFFu)
                             : __uint_as_float(~u);
}
__device__ __forceinline__ float fexp(float x) {
    x = fmaxf(x, -80.0f);
    float t = fmaf(x, 1.4426950408889634f, 12582912.0f);
    float i = t - 12582912.0f;
    float f = fmaf(x, 1.4426950408889634f, -i);
    float p = 1.3333558e-3f;
    p = fmaf(p, f, 9.6181291e-3f);
    p = fmaf(p, f, 5.5504110e-2f);
    p = fmaf(p, f, 2.4022651e-1f);
    p = fmaf(p, f, 6.9314718e-1f);
    p = fmaf(p, f, 1.0f);
    int ei = __float_as_int(t) - 0x4B400000;
    float sc = __int_as_float((ei + 127) << 23);
    return sc * p;
}
__device__ __forceinline__ uint32_t smem_u32(const void* p) {
    uint32_t a;
    asm("{ .reg .u64 t; cvta.to.shared.u64 t, %1; cvt.u32.u64 %0, t; }"
        : "=r"(a) : "l"(p));
    return a;
}
__device__ __forceinline__ uint32_t sw128(uint32_t o) { return o ^ ((o >> 3) & 0x70); }
__device__ __forceinline__ uint32_t pb2(float a, float b) {
    __nv_bfloat162 t = __floats2bfloat162_rn(a, b);
    return *reinterpret_cast<uint32_t*>(&t);
}
__device__ __forceinline__ void st_cs4(float* p, float4 x) {
    asm volatile("st.global.cs.v4.f32 [%0], {%1, %2, %3, %4};"
                 :: "l"(p), "f"(x.x), "f"(x.y), "f"(x.z), "f"(x.w) : "memory");
}

// split grid barrier
__device__ __forceinline__ void g_arrive() {
    __syncthreads();
    if (threadIdx.x == 0)
        asm volatile("red.release.gpu.global.add.u32 [%0], 1;"
                     :: "l"(&g_bcnt) : "memory");
}
__device__ __forceinline__ void g_wait(unsigned int target) {
    if (threadIdx.x == 0) {
        unsigned int v;
        do {
            __nanosleep(32);
            asm volatile("ld.global.acquire.gpu.b32 %0, [%1];"
                         : "=r"(v) : "l"(&g_bcnt) : "memory");
        } while ((int)(v - target) < 0);
    }
    __syncthreads();
}

#define CP_ASYNC16(dst, src) \
    asm volatile("cp.async.cg.shared.global [%0], [%1], 16;" :: "r"(dst), "l"(src) : "memory")
#define CP_COMMIT() asm volatile("cp.async.commit_group;" ::: "memory")
#define CP_WAIT(n)  asm volatile("cp.async.wait_group %0;" :: "n"(n) : "memory")

__device__ __forceinline__ void ldsm4(uint32_t* r, uint32_t addr) {
    asm volatile("ldmatrix.sync.aligned.m8n8.x4.shared.b16 {%0,%1,%2,%3}, [%4];"
                 : "=r"(r[0]), "=r"(r[1]), "=r"(r[2]), "=r"(r[3]) : "r"(addr));
}
__device__ __forceinline__ void ldsm2(uint32_t* r, uint32_t addr) {
    asm volatile("ldmatrix.sync.aligned.m8n8.x2.shared.b16 {%0,%1}, [%2];"
                 : "=r"(r[0]), "=r"(r[1]) : "r"(addr));
}
__device__ __forceinline__ void mma16816(float* d, const uint32_t* a, const uint32_t* b) {
    asm volatile(
        "mma.sync.aligned.m16n8k16.row.col.f32.bf16.bf16.f32 "
        "{%0,%1,%2,%3}, {%4,%5,%6,%7}, {%8,%9}, {%0,%1,%2,%3};"
        : "+f"(d[0]), "+f"(d[1]), "+f"(d[2]), "+f"(d[3])
        : "r"(a[0]), "r"(a[1]), "r"(a[2]), "r"(a[3]), "r"(b[0]), "r"(b[1]));
}

// ---------------- staging: 64 x 64 fp32 -> hi/lo bf16 SW128 (lstm only) ----------------
__device__ __forceinline__ void stsX(uint32_t abase, const float4* av) {
    int t = threadIdx.x;
#pragma unroll
    for (int n = 0; n < 4; n++) {
        int i = t + n * 256;
        int r = i >> 4, q = i & 15;
        float4 x = av[n];
        float hx = __bfloat162float(__float2bfloat16_rn(x.x));
        float hy = __bfloat162float(__float2bfloat16_rn(x.y));
        float hz = __bfloat162float(__float2bfloat16_rn(x.z));
        float hw = __bfloat162float(__float2bfloat16_rn(x.w));
        uint32_t so = sw128((uint32_t)(r * 128 + q * 8));
        asm volatile("st.shared.v2.b32 [%0], {%1, %2};" ::
                     "r"(abase + so), "r"(pb2(hx, hy)), "r"(pb2(hz, hw)) : "memory");
        asm volatile("st.shared.v2.b32 [%0], {%1, %2};" ::
                     "r"(abase + 8192 + so),
                     "r"(pb2(x.x - hx, x.y - hy)), "r"(pb2(x.z - hz, x.w - hw)) : "memory");
    }
}

// ---------------- phase A1: tensor-core LSTM, BK=128 (7 outer chunks) ----------------
__device__ __forceinline__ void issueLB2(uint32_t lbbase, int o, int i0) {
    int t = threadIdx.x;
#pragma unroll
    for (int n = 0; n < 2; n++) {
        int i = t + n * 256;
        if (i < 384) {
            int sub = (i >= 192) ? 1 : 0;
            int ii = i - sub * 192;
            int row = ii >> 3, j = ii & 7;
            size_t g = ((size_t)i0 * 24 + row) * 896 + (size_t)(2 * o + sub) * 64 + j * 8;
            uint32_t dst = lbbase + sub * 6144 + sw128((uint32_t)(row * 128 + j * 16));
            CP_ASYNC16(dst, g_Wlh + g);
            CP_ASYNC16(dst + 3072, g_Wll + g);
        }
    }
}
__device__ __forceinline__ void ldgX(const float* __restrict__ emb,
                                     const float* __restrict__ hin,
                                     const int* sidx, int sc, float4* av) {
    int t = threadIdx.x;
#pragma unroll
    for (int n = 0; n < 4; n++) {
        int i = t + n * 256;
        int r = i >> 4, q = i & 15;
        int k = sc * 64 + q * 4;
        float4 x;
        if (k < EMB) {
            x = *(const float4*)(emb + (size_t)sidx[r] * EMB + k);
            x.x = fmaxf(x.x, 0.f); x.y = fmaxf(x.y, 0.f);
            x.z = fmaxf(x.z, 0.f); x.w = fmaxf(x.w, 0.f);
        } else if (k < EMB + HID) {
            x = __ldcg((const float4*)(hin + r * HID + (k - EMB)));
        } else {
            x = make_float4(0.f, 0.f, 0.f, 0.f);
        }
        av[n] = x;
    }
}

__device__ void lstm_phase(char* smb, uint32_t base,
                           const float* __restrict__ emb,
                           const float* __restrict__ b_ih,
                           const float* __restrict__ b_hh,
                           const int*   __restrict__ qix,
                           int par) {
    float* gsf = (float*)(smb + OFF_GS);    // [24][68]
    float* bsf = (float*)(smb + OFF_BS);    // [24]
    int* sidx  = (int*)(smb + OFF_IDX);

    const int t  = threadIdx.x;
    const int i0 = blockIdx.x;
    const int NU = (i0 < 12) ? 5 : 4;
    const int NR = NU * 4;

    const float* hin  = g_hbuf[par];
    float*       hout = g_hbuf[par ^ 1];

    if (t < BSZ) {
        unsigned long long key = __ldcg(&g_amax[par ^ 1][t]);
        sidx[t] = qix[~(unsigned int)(key & 0xFFFFFFFFull)];
    }
    if (i0 == 0 && t >= 64 && t < 128) g_amax[par][t - 64] = 0ull;
    if (t < 24) {
        float v = 0.f;
        if (t < NR) {
            int gr = (t & 3) * HID + ((t >> 2) * 125 + i0);
            v = b_ih[gr] + b_hh[gr];
        }
        bsf[t] = v;
    }

    const int wid = t >> 5, ln = t & 31;
    const int mt = wid & 3;
    const int n0 = (wid >> 2) * 8;
    const bool extra = (NR == 20) && (wid < 4);

    float acc[4]  = {0.f, 0.f, 0.f, 0.f};
    float acc2[4] = {0.f, 0.f, 0.f, 0.f};

    __syncthreads();   // sidx ready

    issueLB2(base + OFF_LB, 0, i0);
    CP_COMMIT();
    {
        float4 a0[4];
        ldgX(emb, hin, sidx, 0, a0); stsX(base, a0);
        ldgX(emb, hin, sidx, 1, a0); stsX(base + 16384, a0);
    }

    const int ti = ln >> 3, li = ln & 7;
    const int aml = (ti & 1) * 8 + li, ak = ti >> 1;
    const int bli = ln & 7, bsel = (ln >> 3) & 1;

    float4 ava[4], avb[4];
    for (int o = 0; o < 7; o++) {
        if (o < 6) {
            issueLB2(base + OFF_LB + ((o + 1) & 1) * 12288, o + 1, i0);
            CP_COMMIT();
            ldgX(emb, hin, sidx, 2 * o + 2, ava);
            ldgX(emb, hin, sidx, 2 * o + 3, avb);
            CP_WAIT(1);
        } else {
            CP_WAIT(0);
        }
        __syncthreads();

        uint32_t LBo = base + OFF_LB + (o & 1) * 12288;
#pragma unroll
        for (int k8 = 0; k8 < 8; k8++) {
            int sub = k8 >> 2, kss = k8 & 3;
            uint32_t Ahi = base + sub * 16384, Alo = Ahi + 8192;
            uint32_t Bhi = LBo + sub * 6144, Blo = Bhi + 3072;
            uint32_t ah[4], al[4], bh[2], bl[2];
            uint32_t aoff = sw128((uint32_t)((mt * 16 + aml) * 128 + kss * 32 + ak * 16));
            ldsm4(ah, Ahi + aoff);
            ldsm4(al, Alo + aoff);
            uint32_t boff = sw128((uint32_t)((n0 + bli) * 128 + kss * 32 + bsel * 16));
            ldsm2(bh, Bhi + boff);
            ldsm2(bl, Blo + boff);
            mma16816(acc, ah, bh);
            mma16816(acc, ah, bl);
            mma16816(acc, al, bh);
            if (extra) {
                uint32_t boff2 = sw128((uint32_t)((16 + bli) * 128 + kss * 32 + bsel * 16));
                ldsm2(bh, Bhi + boff2);
                ldsm2(bl, Blo + boff2);
                mma16816(acc2, ah, bh);
                mma16816(acc2, ah, bl);
                mma16816(acc2, al, bh);
            }
        }
        __syncthreads();
        if (o < 6) {
            stsX(base, ava);
            stsX(base + 16384, avb);
        }
    }

    // epilogue: frags -> gates smem (+bias)
    {
        int g = ln >> 2, c2 = (ln & 3) * 2;
        int row = mt * 16 + g;
        int col = n0 + c2;
        gsf[col * 68 + row]           = acc[0] + bsf[col];
        gsf[(col + 1) * 68 + row]     = acc[1] + bsf[col + 1];
        gsf[col * 68 + row + 8]       = acc[2] + bsf[col];
        gsf[(col + 1) * 68 + row + 8] = acc[3] + bsf[col + 1];
        if (extra) {
            int col2 = 16 + c2;
            gsf[col2 * 68 + row]           = acc2[0] + bsf[col2];
            gsf[(col2 + 1) * 68 + row]     = acc2[1] + bsf[col2 + 1];
            gsf[col2 * 68 + row + 8]       = acc2[2] + bsf[col2];
            gsf[(col2 + 1) * 68 + row + 8] = acc2[3] + bsf[col2 + 1];
        }
    }
    __syncthreads();

    // cell update + h split write (units exclusively owned per CTA)
    __nv_bfloat16* hhi = g_hhi[par ^ 1];
    __nv_bfloat16* hlo = g_hlo[par ^ 1];
    for (int p = t; p < NU * 64; p += 256) {
        int uu = p >> 6, m = p & 63;
        float gi = gsf[(uu * 4 + 0) * 68 + m];
        float gf = gsf[(uu * 4 + 1) * 68 + m];
        float gg = gsf[(uu * 4 + 2) * 68 + m];
        float go = gsf[(uu * 4 + 3) * 68 + m];
        int ci = m * HID + uu * 125 + i0;
        float c  = __ldcg(&g_c[ci]);
        float si = 1.f / (1.f + expf(-gi));
        float sf = 1.f / (1.f + expf(-gf));
        float so = 1.f / (1.f + expf(-go));
        float nc = sf * c + si * tanhf(gg);
        float nh = so * tanhf(nc);
        g_c[ci]  = nc;
        hout[ci] = nh;
        __nv_bfloat16 hh = __float2bfloat16_rn(nh);
        hhi[ci] = hh;
        hlo[ci] = __float2bfloat16_rn(nh - __bfloat162float(hh));
    }
    // caller's g_arrive() does the closing __syncthreads
}

// ---------------- phase A2: finalize tile in smem -> out ----------------
__device__ void finalize_tile(char* smb, float* __restrict__ out,
                              int sprev, int steps) {
    const int t = threadIdx.x;
    const int w = t >> 5, ln = t & 31;
    const int pp = sprev & 1;
    const int v0 = blockIdx.x * 256;
    float* tile = (float*)(smb + OFF_TILE);
    float* lse_sm = (float*)(smb + OFF_RED);

    for (int r = w; r < BSZ; r += 8) {
        float2 pv[4];
#pragma unroll
        for (int i = 0; i < 4; i++) {
            int idx = ln + i * 32;
            pv[i] = (idx < NBLK) ? __ldcg(&g_part[pp][r][idx])
                                 : make_float2(-3.4e38f, 0.f);
        }
        float m = fmaxf(fmaxf(pv[0].x, pv[1].x), fmaxf(pv[2].x, pv[3].x));
#pragma unroll
        for (int o = 16; o >= 1; o >>= 1)
            m = fmaxf(m, __shfl_xor_sync(0xFFFFFFFFu, m, o));
        float s = pv[0].y * fexp(pv[0].x - m) + pv[1].y * fexp(pv[1].x - m)
                + pv[2].y * fexp(pv[2].x - m) + pv[3].y * fexp(pv[3].x - m);
#pragma unroll
        for (int o = 16; o >= 1; o >>= 1)
            s += __shfl_xor_sync(0xFFFFFFFFu, s, o);
        if (ln == 0) lse_sm[r] = m + logf(s);
    }
    __syncthreads();

#pragma unroll 4
    for (int it = 0; it < 16; it++) {
        int idx = t + it * 256;
        int r  = idx >> 6;
        int c4 = idx & 63;
        float4 x = *(const float4*)&tile[r * 256 + c4 * 4];
        float lse = lse_sm[r];
        x.x -= lse; x.y -= lse; x.z -= lse; x.w -= lse;
        st_cs4(out + ((size_t)r * steps + sprev) * VQ + v0 + c4 * 4, x);
    }
    __syncthreads();   // TILE fully read before buf1 reuse
}

// ---------------- phase B: logits GEMM + fragment epilogue ----------------
__device__ __forceinline__ void issueB(uint32_t bbase, int c, int v0) {
    int t = threadIdx.x;
#pragma unroll
    for (int n = 0; n < 8; n++) {
        int i = t + n * 256;
        int r = i >> 3, j = i & 7;
        size_t g = (size_t)(v0 + r) * HID + (size_t)c * 64 + j * 8;
        uint32_t so = sw128((uint32_t)(r * 128 + j * 16));
        CP_ASYNC16(bbase + so, g_Whi + g);
        CP_ASYNC16(bbase + 32768 + so, g_Wlo + g);
    }
}
// A chunk via cp.async from pre-split h
__device__ __forceinline__ void issueA(uint32_t abase, int c,
                                       const __nv_bfloat16* hhi,
                                       const __nv_bfloat16* hlo) {
    int t = threadIdx.x;
#pragma unroll
    for (int n = 0; n < 2; n++) {
        int i = t + n * 256;
        int r = i >> 3, j = i & 7;
        size_t g = (size_t)r * HID + (size_t)c * 64 + j * 8;
        uint32_t so = sw128((uint32_t)(r * 128 + j * 16));
        CP_ASYNC16(abase + so, hhi + g);
        CP_ASYNC16(abase + 8192 + so, hlo + g);
    }
}

// entry: B chunk 0 resident in Bbuf0 (drained by lstm's CP_WAITs).
__device__ void logits_phase(char* smb, uint32_t base, int par) {
    const int t  = threadIdx.x;
    const int wid = t >> 5, ln = t & 31;
    const int v0 = blockIdx.x * 256;
    const __nv_bfloat16* hhi = g_hhi[par ^ 1];
    const __nv_bfloat16* hlo = g_hlo[par ^ 1];
    float* bias_sm = (float*)(smb + OFF_BIAS);

    float acc[4][4][4];
#pragma unroll
    for (int a = 0; a < 4; a++)
#pragma unroll
        for (int b = 0; b < 4; b++)
#pragma unroll
            for (int cc = 0; cc < 4; cc++) acc[a][b][cc] = 0.f;

    issueA(base, 0, hhi, hlo);
    CP_COMMIT();

    const int ti = ln >> 3, li = ln & 7;
    const int aml = (ti & 1) * 8 + li, ak = ti >> 1;
    const int bnl = (ti >> 1) * 8 + li, bk = ti & 1;
    const int nbase = wid * 32;

    for (int c = 0; c < NCHUNK; c++) {
        int b = c & 1;
        CP_WAIT(0);            // chunk c A+B complete
        __syncthreads();       // orders prev-iteration reads before next issues
        if (c < NCHUNK - 1) {
            issueA(base + (b ^ 1) * 16384, c + 1, hhi, hlo);
            issueB(base + OFF_B + (b ^ 1) * 65536, c + 1, v0);
            CP_COMMIT();
        }

        uint32_t Ahi = base + b * 16384, Alo = Ahi + 8192;
        uint32_t Bhi = base + OFF_B + b * 65536, Blo = Bhi + 32768;
#pragma unroll
        for (int ks = 0; ks < 4; ks++) {
            uint32_t ah[4][4], al[4][4], bh[4][2], bl[4][2];
#pragma unroll
            for (int mt = 0; mt < 4; mt++) {
                uint32_t off = sw128((uint32_t)((mt * 16 + aml) * 128 + ks * 32 + ak * 16));
                ldsm4(ah[mt], Ahi + off);
                ldsm4(al[mt], Alo + off);
            }
#pragma unroll
            for (int ng = 0; ng < 2; ng++) {
                uint32_t off = sw128((uint32_t)((nbase + ng * 16 + bnl) * 128 + ks * 32 + bk * 16));
                uint32_t r4[4];
                ldsm4(r4, Bhi + off);
                bh[ng * 2][0] = r4[0]; bh[ng * 2][1] = r4[1];
                bh[ng * 2 + 1][0] = r4[2]; bh[ng * 2 + 1][1] = r4[3];
                ldsm4(r4, Blo + off);
                bl[ng * 2][0] = r4[0]; bl[ng * 2][1] = r4[1];
                bl[ng * 2 + 1][0] = r4[2]; bl[ng * 2 + 1][1] = r4[3];
            }
#pragma unroll
            for (int mt = 0; mt < 4; mt++)
#pragma unroll
                for (int nt = 0; nt < 4; nt++) {
                    mma16816(acc[mt][nt], ah[mt], bh[nt]);
                    mma16816(acc[mt][nt], ah[mt], bl[nt]);
                    mma16816(acc[mt][nt], al[mt], bh[nt]);
                }
        }
    }

    // epilogue from fragments: tile store + per-warp slab partials
    __syncthreads();
    float* tile = (float*)(smb + OFF_TILE);
    unsigned long long* pmk = (unsigned long long*)(smb + OFF_GS);  // [64][8]
    float* pms = (float*)(smb + OFF_GS + 4096);                     // [64][8]
    const int g = ln >> 2, tg2 = (ln & 3) * 2;
#pragma unroll
    for (int mt = 0; mt < 4; mt++) {
#pragma unroll
        for (int half = 0; half < 2; half++) {
            int r = mt * 16 + g + half * 8;
            float vals[8];
#pragma unroll
            for (int nt = 0; nt < 4; nt++) {
                int col = nbase + nt * 8 + tg2;
                float va = acc[mt][nt][half * 2]     + bias_sm[col];
                float vb = acc[mt][nt][half * 2 + 1] + bias_sm[col + 1];
                vals[nt * 2] = va; vals[nt * 2 + 1] = vb;
                tile[r * 256 + col]     = va;
                tile[r * 256 + col + 1] = vb;
            }
            float vm = vals[0]; int vj = 0;
#pragma unroll
            for (int j = 1; j < 8; j++)
                if (vals[j] > vm) { vm = vals[j]; vj = j; }
            int vcol = v0 + nbase + (vj >> 1) * 8 + tg2 + (vj & 1);
            unsigned long long key =
                ((unsigned long long)fmono(vm) << 32) |
                (unsigned int)(~(unsigned int)vcol);
            {
                unsigned long long o1 = __shfl_xor_sync(0xFFFFFFFFu, key, 1);
                if (o1 > key) key = o1;
                unsigned long long o2 = __shfl_xor_sync(0xFFFFFFFFu, key, 2);
                if (o2 > key) key = o2;
            }
            float mrow = fmono_inv((unsigned int)(key >> 32));
            float s = 0.f;
#pragma unroll
            for (int j = 0; j < 8; j++) s += fexp(vals[j] - mrow);
            s += __shfl_xor_sync(0xFFFFFFFFu, s, 1);
            s += __shfl_xor_sync(0xFFFFFFFFu, s, 2);
            if ((ln & 3) == 0) {
                pmk[r * 8 + wid] = key;
                pms[r * 8 + wid] = s;
            }
        }
    }
    __syncthreads();

    if (t < 64) {
        unsigned long long key = pmk[t * 8];
#pragma unroll
        for (int i = 1; i < 8; i++) {
            unsigned long long o2 = pmk[t * 8 + i];
            if (o2 > key) key = o2;
        }
        float M = fmono_inv((unsigned int)(key >> 32));
        float s = 0.f;
#pragma unroll
        for (int i = 0; i < 8; i++) {
            float mi = fmono_inv((unsigned int)(pmk[t * 8 + i] >> 32));
            s += pms[t * 8 + i] * fexp(mi - M);
        }
        atomicMax(&g_amax[par][t], key);
        g_part[par][t][blockIdx.x] = make_float2(M, s);
    }
    // caller's g_arrive() does the closing __syncthreads
}

// ---------------- the persistent decode kernel (single launch) ----------------
__global__ void __launch_bounds__(256, 1)
k_main(const float* __restrict__ q_att,
       const float* __restrict__ emb,
       const float* __restrict__ W_ih,
       const float* __restrict__ W_hh,
       const float* __restrict__ b_ih,
       const float* __restrict__ b_hh,
       const float* __restrict__ out_W,
       const float* __restrict__ out_b,
       const int*   __restrict__ qix,
       float* __restrict__ out, int steps) {
    extern __shared__ __align__(16) char smem_raw[];
    uint32_t raw  = smem_u32(smem_raw);
    uint32_t base = (raw + 1023) & ~1023u;
    char* smb = smem_raw + (base - raw);
    const int t = threadIdx.x;
    const int v0cta = blockIdx.x * 256;

    unsigned int Eval = 0, ebase = 0;
    int nb = 0;
    const unsigned int NBAR = (unsigned int)(1 + 2 * steps);
    if (t == 0) {
        asm volatile("ld.global.acquire.gpu.b32 %0, [%1];"
                     : "=r"(Eval) : "l"(&g_epoch));
        ebase = Eval * NBAR * NCTA;
    }

    // ---- prologue ----
    {
        size_t n4 = (size_t)VQ * HID / 4;
        uint2* whi = (uint2*)g_Whi;
        uint2* wlo = (uint2*)g_Wlo;
        for (size_t i = (size_t)blockIdx.x * 256 + t; i < n4; i += (size_t)NCTA * 256) {
            float4 x = ((const float4*)out_W)[i];
            float hx = __bfloat162float(__float2bfloat16_rn(x.x));
            float hy = __bfloat162float(__float2bfloat16_rn(x.y));
            float hz = __bfloat162float(__float2bfloat16_rn(x.z));
            float hw = __bfloat162float(__float2bfloat16_rn(x.w));
            whi[i] = make_uint2(pb2(hx, hy), pb2(hz, hw));
            wlo[i] = make_uint2(pb2(x.x - hx, x.y - hy), pb2(x.z - hz, x.w - hw));
        }
        {
            int NRp = ((blockIdx.x < 12) ? 5 : 4) * 4;
            for (int i = t; i < 24 * 896; i += 256) {
                int r = i / 896, k = i - r * 896;
                float v = 0.f;
                if (r < NRp && k < EMB + HID) {
                    int gr = (r & 3) * HID + ((r >> 2) * 125 + blockIdx.x);
                    v = (k < EMB) ? W_ih[(size_t)gr * EMB + k]
                                  : W_hh[(size_t)gr * HID + (k - EMB)];
                }
                float hv = __bfloat162float(__float2bfloat16_rn(v));
                size_t o = ((size_t)blockIdx.x * 24 + r) * 896 + k;
                g_Wlh[o] = __float2bfloat16_rn(v);
                g_Wll[o] = __float2bfloat16_rn(v - hv);
            }
        }
        if (blockIdx.x == 0) {
            if (t < BSZ) {
                g_amax[1][t] = (unsigned long long)(unsigned int)(~(unsigned int)SOS);
                g_amax[0][t] = 0ull;
            }
            for (int i = t; i < BSZ * HID; i += 256) {
                float v = q_att[i];
                g_hbuf[0][i] = v;
                g_c[i] = 0.f;
                __nv_bfloat16 hh = __float2bfloat16_rn(v);
                g_hhi[0][i] = hh;
                g_hlo[0][i] = __float2bfloat16_rn(v - __bfloat162float(hh));
            }
        }
        ((float*)(smb + OFF_BIAS))[t] = out_b[v0cta + t];
    }
    ++nb; g_arrive(); g_wait(ebase + nb * NCTA);

    // logits chunk 0 for step 0 -> Bbuf0 (drains during lstm)
    issueB(base + OFF_B, 0, v0cta);
    CP_COMMIT();

    for (int s = 0; s < steps; s++) {
        int par = s & 1;

        lstm_phase(smb, base, emb, b_ih, b_hh, qix, par);
        ++nb; g_arrive();
        if (s > 0) finalize_tile(smb, out, s - 1, steps);
        g_wait(ebase + nb * NCTA);

        logits_phase(smb, base, par);
        ++nb; g_arrive();
        if (s + 1 < steps) {
            issueB(base + OFF_B, 0, v0cta);      // next step's B chunk 0 -> Bbuf0
            CP_COMMIT();
        }
        g_wait(ebase + nb * NCTA);
    }

    if (blockIdx.x == 0 && t == 0)
        *((volatile unsigned int*)&g_epoch) = Eval + 1;

    finalize_tile(smb, out, steps - 1, steps);
}

// ---------------- launch ----------------
extern "C" void kernel_launch(void* const* d_in, const int* in_sizes, int n_in,
                              void* d_out, int out_size) {
    (void)in_sizes; (void)n_in;
    const float* q_att = (const float*)d_in[1];
    const float* emb   = (const float*)d_in[2];
    const float* W_ih  = (const float*)d_in[3];
    const float* W_hh  = (const float*)d_in[4];
    const float* b_ih  = (const float*)d_in[5];
    const float* b_hh  = (const float*)d_in[6];
    const float* out_W = (const float*)d_in[7];
    const float* out_b = (const float*)d_in[8];
    const int*   qix   = (const int*)d_in[9];

    int steps = out_size / (BSZ * VQ);  // 33

    cudaFuncSetAttribute(k_main, cudaFuncAttributeMaxDynamicSharedMemorySize,
                         SMEM_REQ);

    k_main<<<NCTA, 256, SMEM_REQ>>>(q_att, emb, W_ih, W_hh, b_ih, b_hh,
                                    out_W, out_b, qix, (float*)d_out, steps);
}